// round 15
// baseline (speedup 1.0000x reference)
#include <cuda_runtime.h>
#include <cuda_fp16.h>
#include <stdint.h>
#include <math.h>

#define B_ 8
#define T_ 2048
#define D_ 512
#define NH_ 8
#define DH_ 64
#define L_ 4
#define UP_ 704
#define EPS_ 1e-5f
#define NTOK_ (B_*T_)

// ---------------- static device scratch (no allocation allowed) -------------
__device__ float g_x [(size_t)NTOK_*D_];
__device__ float g_xn[(size_t)NTOK_*D_];
__device__ float g_xc[(size_t)NTOK_*D_];
__device__ float g_gates[(size_t)T_*B_*NH_*4*DH_];
__device__ float g_h [(size_t)NTOK_*D_];
__device__ float g_ge[(size_t)NTOK_*UP_];
__device__ float g_wui[(size_t)L_*D_*2*UP_];   // interleaved w_up copy

// ---------------- packed helpers ----------------------------------------------
#define FMA2(acc,xx,yy) asm("fma.rn.f32x2 %0,%1,%2,%0;" : "+l"(acc) : "l"(xx),"l"(yy))
#define PACK2(d,s)      asm("mov.b64 %0, {%1,%1};" : "=l"(d) : "f"(s))
#define UNPK2(lo,hi,p)  asm("mov.b64 {%0,%1},%2;" : "=f"(lo),"=f"(hi) : "l"(p))
__device__ __forceinline__ float sum2(unsigned long long p){
    float a,b; asm("mov.b64 {%0,%1},%2;" : "=f"(a),"=f"(b) : "l"(p)); return a+b;
}
__device__ __forceinline__ uint32_t f2h2(float lo, float hi){
    uint32_t r; asm("cvt.rn.f16x2.f32 %0, %1, %2;" : "=r"(r) : "f"(hi), "f"(lo)); return r;
}
__device__ __forceinline__ uint32_t smem_u32(const void* p){
    uint32_t a; asm("{ .reg .u64 t; cvta.to.shared.u64 t, %1; cvt.u32.u64 %0, t; }"
                    : "=r"(a) : "l"(p));
    return a;
}
__device__ __forceinline__ void ldsm4(uint32_t& r0,uint32_t& r1,uint32_t& r2,uint32_t& r3,
                                      uint32_t addr){
    asm volatile("ldmatrix.sync.aligned.m8n8.x4.shared.b16 {%0,%1,%2,%3}, [%4];"
        : "=r"(r0),"=r"(r1),"=r"(r2),"=r"(r3) : "r"(addr));
}
__device__ __forceinline__ void mma16(float* c, uint32_t a0,uint32_t a1,uint32_t a2,uint32_t a3,
                                      uint32_t b0,uint32_t b1){
    asm volatile("mma.sync.aligned.m16n8k16.row.col.f32.f16.f16.f32 "
                 "{%0,%1,%2,%3},{%4,%5,%6,%7},{%8,%9},{%0,%1,%2,%3};\n"
                 : "+f"(c[0]),"+f"(c[1]),"+f"(c[2]),"+f"(c[3])
                 : "r"(a0),"r"(a1),"r"(a2),"r"(a3),"r"(b0),"r"(b1));
}
__device__ __forceinline__ float gelu_f(float x){
    return 0.5f*x*(1.f+erff(x*0.70710678118654752f));
}

// named barriers for the scan's producer/consumer split
__device__ __forceinline__ void bar_sync1()  { asm volatile("bar.sync 1, 256;"   ::: "memory"); }
__device__ __forceinline__ void bar_arrive1(){ asm volatile("bar.arrive 1, 256;" ::: "memory"); }
__device__ __forceinline__ void bar_sync2()  { asm volatile("bar.sync 2, 256;"   ::: "memory"); }

// ------- w_up column interleave: dst[..][c'] = src[..][c] ---------------------
__global__ void k_ilv(const float* __restrict__ src, float* __restrict__ dst){
    size_t i = (size_t)blockIdx.x*256 + threadIdx.x;
    int c = (int)(i % (2*UP_));
    size_t rl = i / (2*UP_);
    int cr = (c < UP_) ? 2*c : 2*(c-UP_)+1;
    dst[rl*(2*UP_) + cr] = src[i];
}

// ---------------- elementwise kernels ----------------------------------------
__global__ void k_mask(const float* __restrict__ x, const unsigned char* __restrict__ mask,
                       float* __restrict__ out){
    int i = blockIdx.x*256 + threadIdx.x;
    float4 v = ((const float4*)x)[i];
    if (mask[i>>7]) { v.x=0.f; v.y=0.f; v.z=0.f; v.w=0.f; }
    ((float4*)out)[i] = v;
}

__global__ void k_ln(const float* __restrict__ in, const float* __restrict__ w,
                     float* __restrict__ out){
    int tok = blockIdx.x, tid = threadIdx.x;
    float4 v = ((const float4*)(in + (size_t)tok*D_))[tid];
    float s  = v.x+v.y+v.z+v.w;
    float sq = v.x*v.x+v.y*v.y+v.z*v.z+v.w*v.w;
    #pragma unroll
    for (int o=16;o>0;o>>=1){ s += __shfl_xor_sync(0xffffffffu,s,o); sq += __shfl_xor_sync(0xffffffffu,sq,o); }
    __shared__ float sb[8];
    int warp=tid>>5, lane=tid&31;
    if (lane==0){ sb[warp]=s; sb[4+warp]=sq; }
    __syncthreads();
    s  = sb[0]+sb[1]+sb[2]+sb[3];
    sq = sb[4]+sb[5]+sb[6]+sb[7];
    float mu  = s*(1.f/(float)D_);
    float var = sq*(1.f/(float)D_) - mu*mu;
    float r = rsqrtf(var + EPS_);
    float4 wv = ((const float4*)w)[tid];
    float4 o4;
    o4.x=(v.x-mu)*r*wv.x; o4.y=(v.y-mu)*r*wv.y; o4.z=(v.z-mu)*r*wv.z; o4.w=(v.w-mu)*r*wv.w;
    ((float4*)(out + (size_t)tok*D_))[tid] = o4;
}

__global__ void k_conv(const float* __restrict__ xn, const float* __restrict__ cw,
                       const float* __restrict__ cb, float* __restrict__ xc){
    int i = blockIdx.x*256 + threadIdx.x;
    int tok = i >> 7, d4 = i & 127;
    int b = tok >> 11, t = tok & (T_-1);
    float4 bz = ((const float4*)cb)[d4];
    float ax=bz.x, ay=bz.y, az=bz.z, aw=bz.w;
    #pragma unroll
    for (int k=0;k<4;k++){
        int tt = t + k - 3;
        if (tt >= 0){
            float4 xv = ((const float4*)xn)[(size_t)(((b<<11)+tt)*128 + d4)];
            float4 wv = ((const float4*)cw)[k*128 + d4];
            ax = fmaf(xv.x, wv.x, ax); ay = fmaf(xv.y, wv.y, ay);
            az = fmaf(xv.z, wv.z, az); aw = fmaf(xv.w, wv.w, aw);
        }
    }
    float4 o;
    o.x = ax/(1.f+__expf(-ax));
    o.y = ay/(1.f+__expf(-ay));
    o.z = az/(1.f+__expf(-az));
    o.w = aw/(1.f+__expf(-aw));
    ((float4*)xc)[i] = o;
}

// ------- fused GroupNorm + residual + LayerNorm(ln2) -> fp32 xn ---------------
__global__ void __launch_bounds__(256) k_gnres_ln(const float* __restrict__ h,
    const float* __restrict__ gnw, float* __restrict__ x,
    const float* __restrict__ w2, float* __restrict__ xn)
{
    int tok = blockIdx.x;
    int warp = threadIdx.x>>5, lane = threadIdx.x&31;
    const float2* hp = (const float2*)(h + (size_t)tok*D_ + warp*DH_);
    float2 v = hp[lane];
    float s = v.x+v.y, sq = v.x*v.x+v.y*v.y;
    #pragma unroll
    for (int o=16;o>0;o>>=1){ s += __shfl_xor_sync(0xffffffffu,s,o); sq += __shfl_xor_sync(0xffffffffu,sq,o); }
    float mu = s*(1.f/(float)DH_);
    float var = sq*(1.f/(float)DH_) - mu*mu;
    float r = rsqrtf(var + EPS_);
    float2 gw = ((const float2*)(gnw + warp*DH_))[lane];
    float2* xp = (float2*)(x + (size_t)tok*D_ + warp*DH_);
    float2 xv = xp[lane];
    xv.x += (v.x-mu)*r*gw.x;
    xv.y += (v.y-mu)*r*gw.y;
    xp[lane] = xv;

    float s2 = xv.x+xv.y, q2 = xv.x*xv.x+xv.y*xv.y;
    #pragma unroll
    for (int o=16;o>0;o>>=1){ s2 += __shfl_xor_sync(0xffffffffu,s2,o); q2 += __shfl_xor_sync(0xffffffffu,q2,o); }
    __shared__ float sb[16];
    if (lane==0){ sb[warp]=s2; sb[8+warp]=q2; }
    __syncthreads();
    s2 = sb[0]+sb[1]+sb[2]+sb[3]+sb[4]+sb[5]+sb[6]+sb[7];
    q2 = sb[8]+sb[9]+sb[10]+sb[11]+sb[12]+sb[13]+sb[14]+sb[15];
    float mu2  = s2*(1.f/(float)D_);
    float var2 = q2*(1.f/(float)D_) - mu2*mu2;
    float r2 = rsqrtf(var2 + EPS_);
    float2 lw = ((const float2*)(w2 + warp*DH_))[lane];
    float2 o2;
    o2.x = (xv.x-mu2)*r2*lw.x;
    o2.y = (xv.y-mu2)*r2*lw.y;
    ((float2*)(xn + (size_t)tok*D_ + warp*DH_))[lane] = o2;
}

// ------- gate projections: register-tiled fp32 GEMM (unchanged) --------------
__global__ void __launch_bounds__(256) k_gates(const float* __restrict__ xc,
    const float* __restrict__ xn, const float* __restrict__ Wg_l,
    const float* __restrict__ bg_l, float* __restrict__ gates)
{
    __shared__ float in_t[64][64];
    __shared__ float w_s[64][128];
    const int tok0 = blockIdx.x * 64;
    const int h    = blockIdx.y;
    const int z    = blockIdx.z;
    const int tid  = threadIdx.x;
    const float* src = z ? xn : xc;

    {
        const int tok_l = tid >> 2;
        const int kq    = (tid & 3) * 16;
        const float* sp = src + (size_t)(tok0+tok_l)*D_ + h*64 + kq;
        #pragma unroll
        for (int j=0;j<4;j++){
            float4 v = *(const float4*)(sp + j*4);
            in_t[kq+j*4+0][tok_l] = v.x;
            in_t[kq+j*4+1][tok_l] = v.y;
            in_t[kq+j*4+2][tok_l] = v.z;
            in_t[kq+j*4+3][tok_l] = v.w;
        }
    }
    {
        const int r   = tid >> 1;
        const int kq2 = (tid & 1) * 32;
        const float* wrow = Wg_l + ((size_t)((2*z + (r>>6))*NH_ + h)*64 + (r&63))*64 + kq2;
        #pragma unroll
        for (int j=0;j<8;j++){
            float4 v = *(const float4*)(wrow + j*4);
            w_s[kq2+j*4+0][r] = v.x;
            w_s[kq2+j*4+1][r] = v.y;
            w_s[kq2+j*4+2][r] = v.z;
            w_s[kq2+j*4+3][r] = v.w;
        }
    }
    __syncthreads();

    const int tok0t = (tid >> 5) * 8;
    const int o0    = (tid & 31) * 4;

    unsigned long long acc[16];
    #pragma unroll
    for (int i=0;i<16;i++) acc[i] = 0ull;

    #pragma unroll 16
    for (int k=0;k<64;k++){
        ulonglong2 iA = *(const ulonglong2*)&in_t[k][tok0t];
        ulonglong2 iB = *(const ulonglong2*)&in_t[k][tok0t+4];
        float4 wv = *(const float4*)&w_s[k][o0];
        unsigned long long w0,w1,w2,w3;
        PACK2(w0,wv.x); PACK2(w1,wv.y); PACK2(w2,wv.z); PACK2(w3,wv.w);
        FMA2(acc[ 0], iA.x, w0); FMA2(acc[ 1], iA.x, w1); FMA2(acc[ 2], iA.x, w2); FMA2(acc[ 3], iA.x, w3);
        FMA2(acc[ 4], iA.y, w0); FMA2(acc[ 5], iA.y, w1); FMA2(acc[ 6], iA.y, w2); FMA2(acc[ 7], iA.y, w3);
        FMA2(acc[ 8], iB.x, w0); FMA2(acc[ 9], iB.x, w1); FMA2(acc[10], iB.x, w2); FMA2(acc[11], iB.x, w3);
        FMA2(acc[12], iB.y, w0); FMA2(acc[13], iB.y, w1); FMA2(acc[14], iB.y, w2); FMA2(acc[15], iB.y, w3);
    }

    float4 bias = *(const float4*)(bg_l + (size_t)((2*z + (o0>>6))*NH_ + h)*64 + (o0&63));
    #pragma unroll
    for (int p=0;p<4;p++){
        float lo0,hi0,lo1,hi1,lo2,hi2,lo3,hi3;
        UNPK2(lo0,hi0,acc[p*4+0]);
        UNPK2(lo1,hi1,acc[p*4+1]);
        UNPK2(lo2,hi2,acc[p*4+2]);
        UNPK2(lo3,hi3,acc[p*4+3]);
        #pragma unroll
        for (int half=0;half<2;half++){
            int tok = tok0 + tok0t + p*2 + half;
            int bb = tok >> 11, tt = tok & (T_-1);
            float4 o4;
            o4.x = (half ? hi0 : lo0) + bias.x;
            o4.y = (half ? hi1 : lo1) + bias.y;
            o4.z = (half ? hi2 : lo2) + bias.z;
            o4.w = (half ? hi3 : lo3) + bias.w;
            *(float4*)(gates + (((size_t)tt*B_+bb)*NH_+h)*256 + z*128 + o0) = o4;
        }
    }
}

// ------- sLSTM scan: 2 chains per block (R registers shared across b) ---------
__device__ __forceinline__ float scan_dot(const unsigned long long* Rp,
                                          const float* h_sm, float gp){
    unsigned long long acc[4] = {0ull,0ull,0ull,0ull};
    const ulonglong2* hp = (const ulonglong2*)h_sm;
    #pragma unroll
    for (int j=0;j<16;j++){
        ulonglong2 hv = hp[j];
        FMA2(acc[j&1],     Rp[2*j],   hv.x);
        FMA2(acc[2+(j&1)], Rp[2*j+1], hv.y);
    }
    return sum2(acc[0])+sum2(acc[1])+sum2(acc[2])+sum2(acc[3]) + gp;
}

__device__ __forceinline__ float scan_update(float ip_, float fp_, float zp_, float op_,
                                             float& c, float& n, float& m){
    float en   = __expf(-fp_);
    float sinv = 1.f + en;
    float a    = __expf(ip_ - m);
    float w    = a * sinv;
    bool  p    = (w >= 1.f);
    float iv   = p ? 1.f : w;
    float fv   = p ? __fdividef(1.f, w) : 1.f;
    m = p ? ip_ : (m - __logf(sinv));
    float tz = 1.f - __fdividef(2.f, 1.f + __expf(2.f*zp_));
    c = fv*c + iv*tz;
    n = fv*n + iv;
    return __fdividef(c, n + n*__expf(-op_));
}

__global__ void __launch_bounds__(256) k_scan(const float* __restrict__ Rg_l,
    const float* __restrict__ gates, float* __restrict__ hout)
{
    const int bp = blockIdx.x >> 3, h = blockIdx.x & 7;   // 32 blocks: b-pair x head
    const int tid = threadIdx.x, g = tid >> 6, e = tid & 63;
    __shared__ __align__(16) float h_sm[2][64];
    __shared__ float gsm[512];
    unsigned long long Rp[32];
    {
        const ulonglong2* Rsrc = (const ulonglong2*)(Rg_l + ((size_t)(g*NH_+h)*64 + e)*64);
        #pragma unroll
        for (int i=0;i<16;i++){ ulonglong2 w = Rsrc[i]; Rp[2*i]=w.x; Rp[2*i+1]=w.y; }
    }
    if (tid < 128) h_sm[tid>>6][tid&63] = 0.f;
    float c=0.f, n=0.f, m=0.f;                 // state for update threads (tid<128)
    const size_t tstride = (size_t)B_*NH_*256;
    const float* gb0 = gates + ((size_t)(bp*2)*NH_+h)*256 + tid;
    const float* gb1 = gb0 + (size_t)NH_*256;

    float gbuf0[8], gbuf1[8];
    #pragma unroll
    for (int q=0;q<8;q++){
        gbuf0[q] = __ldg(gb0 + (size_t)q*tstride);
        gbuf1[q] = __ldg(gb1 + (size_t)q*tstride);
    }
    __syncthreads();

    const int uch = tid >> 6, ue = tid & 63;   // update-thread chain/element (tid<128)
    float* hb = hout + ((size_t)(bp*2+uch)*T_)*D_ + h*DH_ + ue;

    for (int t=0; t<T_; t+=8){
        #pragma unroll
        for (int q=0;q<8;q++){
            float gp0 = gbuf0[q], gp1 = gbuf1[q];
            if (t+q+8 < T_){
                gbuf0[q] = __ldg(gb0 + (size_t)(t+q+8)*tstride);
                gbuf1[q] = __ldg(gb1 + (size_t)(t+q+8)*tstride);
            }
            float v0 = scan_dot(Rp, h_sm[0], gp0);
            float v1 = scan_dot(Rp, h_sm[1], gp1);
            gsm[tid]     = v0;
            gsm[256+tid] = v1;
            if (tid >= 128){
                bar_arrive1();
                bar_sync2();
            } else {
                bar_sync1();
                const float* gs = gsm + uch*256;
                float ip_ = gs[ue], fp_ = gs[64+ue], zp_ = gs[128+ue], op_ = gs[192+ue];
                float hv = scan_update(ip_, fp_, zp_, op_, c, n, m);
                h_sm[uch][ue] = hv;
                hb[(size_t)(t+q)*D_] = hv;
                bar_sync2();
            }
        }
    }
}

// ------- fp16 tensor-core GEMM (fp32 staging) + LDSM fragments + fused epi ----
// mode 0: C = A*B    mode 1: Cge = gelu/up pairs (interleaved N)   mode 2: C += A*B
#define KW 20
__global__ void __launch_bounds__(256) k_gemm16(const float* __restrict__ A,
    const float* __restrict__ Bm, float* __restrict__ C, float* __restrict__ Cge,
    int N, int K, int mode)
{
    __shared__ uint32_t As[2][128*KW];
    __shared__ uint32_t Bs[2][128*KW];
    const int m0 = blockIdx.x*128, n0 = blockIdx.y*128;
    const int tid = threadIdx.x;
    const int warp=tid>>5, lane=tid&31, gid=lane>>2, tig=lane&3;
    const int wm=(warp&3)*32, wn=(warp>>2)*64;
    float acc[16][4];
    #pragma unroll
    for (int i=0;i<16;i++){ acc[i][0]=0.f; acc[i][1]=0.f; acc[i][2]=0.f; acc[i][3]=0.f; }

    const int ar  = tid>>3;
    const int ac4 = tid&7;
    const int bn  = tid&127;
    const int bkh = (tid>>7)*16;

    const int rowsel = (lane & 7) + (lane & 8);
    const int colsel = (lane & 16) ? 4 : 0;
    const uint32_t as_base = smem_u32(&As[0][0]);
    const uint32_t bs_base = smem_u32(&Bs[0][0]);

    float4 ra[4]; float rb[16];

    #pragma unroll
    for (int j=0;j<4;j++) ra[j] = *(const float4*)(A + (size_t)(m0+ar+j*32)*K + ac4*4);
    {
        const float* bp = Bm + (size_t)bkh*N + n0 + bn;
        #pragma unroll
        for (int j=0;j<16;j++) rb[j] = bp[(size_t)j*N];
    }
    #pragma unroll
    for (int j=0;j<4;j++){
        uint32_t* dst = &As[0][(ar+j*32)*KW + ac4*2];
        dst[0] = f2h2(ra[j].x, ra[j].y);
        dst[1] = f2h2(ra[j].z, ra[j].w);
    }
    #pragma unroll
    for (int w=0;w<8;w++) Bs[0][bn*KW + (bkh>>1) + w] = f2h2(rb[2*w], rb[2*w+1]);
    __syncthreads();

    const int nk = K >> 5;
    for (int i=0; i<nk; i++){
        const int cur = i&1;
        if (i+1 < nk){
            const int kb = (i+1)*32;
            #pragma unroll
            for (int j=0;j<4;j++) ra[j] = *(const float4*)(A + (size_t)(m0+ar+j*32)*K + kb + ac4*4);
            const float* bp = Bm + (size_t)(kb+bkh)*N + n0 + bn;
            #pragma unroll
            for (int j=0;j<16;j++) rb[j] = bp[(size_t)j*N];
        }
        const uint32_t abuf = as_base + (uint32_t)cur*(128*KW*4);
        const uint32_t bbuf = bs_base + (uint32_t)cur*(128*KW*4);
        #pragma unroll
        for (int ks=0;ks<2;ks++){
            const int k0w = ks*8;
            uint32_t a[2][4];
            #pragma unroll
            for (int mt=0;mt<2;mt++){
                uint32_t addr = abuf + ((wm + mt*16 + rowsel)*KW + k0w + colsel)*4;
                ldsm4(a[mt][0], a[mt][1], a[mt][2], a[mt][3], addr);
            }
            #pragma unroll
            for (int ntp=0;ntp<4;ntp++){
                uint32_t b0e,b0o,b1e,b1o;
                uint32_t addr = bbuf + ((wn + ntp*16 + rowsel)*KW + k0w + colsel)*4;
                ldsm4(b0e, b0o, b1e, b1o, addr);
                const int nt = 2*ntp;
                mma16(acc[nt],     a[0][0],a[0][1],a[0][2],a[0][3], b0e,b1e);
                mma16(acc[8+nt],   a[1][0],a[1][1],a[1][2],a[1][3], b0e,b1e);
                mma16(acc[nt+1],   a[0][0],a[0][1],a[0][2],a[0][3], b0o,b1o);
                mma16(acc[8+nt+1], a[1][0],a[1][1],a[1][2],a[1][3], b0o,b1o);
            }
        }
        if (i+1 < nk){
            const int nxt = cur^1;
            #pragma unroll
            for (int j=0;j<4;j++){
                uint32_t* dst = &As[nxt][(ar+j*32)*KW + ac4*2];
                dst[0] = f2h2(ra[j].x, ra[j].y);
                dst[1] = f2h2(ra[j].z, ra[j].w);
            }
            #pragma unroll
            for (int w=0;w<8;w++) Bs[nxt][bn*KW + (bkh>>1) + w] = f2h2(rb[2*w], rb[2*w+1]);
        }
        __syncthreads();
    }

    if (mode == 1){
        #pragma unroll
        for (int mt=0;mt<2;mt++)
          #pragma unroll
          for (int nt=0;nt<8;nt++){
            int r    = m0 + wm + mt*16 + gid;
            int cidx = n0 + wn + nt*8 + tig*2;
            int j    = cidx >> 1;
            const float* a4 = acc[mt*8+nt];
            Cge[(size_t)r*UP_ + j]     = gelu_f(a4[0]) * a4[1];
            Cge[(size_t)(r+8)*UP_ + j] = gelu_f(a4[2]) * a4[3];
          }
    } else {
        #pragma unroll
        for (int mt=0;mt<2;mt++)
          #pragma unroll
          for (int nt=0;nt<8;nt++){
            int r    = m0 + wm + mt*16 + gid;
            int cidx = n0 + wn + nt*8 + tig*2;
            float* p0 = C + (size_t)r*N + cidx;
            float* p1 = C + (size_t)(r+8)*N + cidx;
            const float* a4 = acc[mt*8+nt];
            if (mode == 2){
                p0[0]+=a4[0]; p0[1]+=a4[1];
                p1[0]+=a4[2]; p1[1]+=a4[3];
            } else {
                p0[0]=a4[0]; p0[1]=a4[1];
                p1[0]=a4[2]; p1[1]=a4[3];
            }
          }
    }
}

// ---------------- launch ------------------------------------------------------
extern "C" void kernel_launch(void* const* d_in, const int* in_sizes, int n_in,
                              void* d_out, int out_size) {
    const float* x        = (const float*)d_in[0];
    const unsigned char* mask = (const unsigned char*)d_in[1];
    const float* ln1_w    = (const float*)d_in[2];
    const float* conv_w   = (const float*)d_in[3];
    const float* conv_b   = (const float*)d_in[4];
    const float* Wg       = (const float*)d_in[5];
    const float* Rg       = (const float*)d_in[6];
    const float* bg       = (const float*)d_in[7];
    const float* gn_w     = (const float*)d_in[8];
    const float* ln2_w    = (const float*)d_in[9];
    const float* w_up     = (const float*)d_in[10];
    const float* w_down   = (const float*)d_in[11];
    const float* post_ln  = (const float*)d_in[12];
    float* out = (float*)d_out;

    float *px,*pxn,*pxc,*pg,*ph,*pge,*pwui;
    cudaGetSymbolAddress((void**)&px,  g_x);
    cudaGetSymbolAddress((void**)&pxn, g_xn);
    cudaGetSymbolAddress((void**)&pxc, g_xc);
    cudaGetSymbolAddress((void**)&pg,  g_gates);
    cudaGetSymbolAddress((void**)&ph,  g_h);
    cudaGetSymbolAddress((void**)&pge, g_ge);
    cudaGetSymbolAddress((void**)&pwui, g_wui);

    k_ilv<<<(L_*D_*2*UP_)/256, 256>>>(w_up, pwui);

    k_mask<<<NTOK_*128/256, 256>>>(x, mask, px);
    for (int l=0; l<L_; l++){
        k_ln<<<NTOK_,128>>>(px, ln1_w + l*D_, pxn);
        k_conv<<<NTOK_*128/256,256>>>(pxn, conv_w + l*4*D_, conv_b + l*D_, pxc);
        dim3 gg(NTOK_/64, NH_, 2);
        k_gates<<<gg,256>>>(pxc, pxn, Wg + (size_t)l*4*NH_*DH_*DH_, bg + l*4*NH_*DH_, pg);
        k_scan<<<32,256>>>(Rg + (size_t)l*4*NH_*DH_*DH_, pg, ph);
        k_gnres_ln<<<NTOK_,256>>>(ph, gn_w + l*D_, px, ln2_w + l*D_, pxn);
        dim3 gu(NTOK_/128, (2*UP_)/128);
        k_gemm16<<<gu,256>>>(pxn, pwui + (size_t)l*D_*2*UP_, nullptr, pge, 2*UP_, D_, 1);
        dim3 gd(NTOK_/128, D_/128);
        k_gemm16<<<gd,256>>>(pge, w_down + (size_t)l*UP_*D_, px, nullptr, D_, UP_, 2);
    }
    k_ln<<<NTOK_,128>>>(px, post_ln, out);
}

// round 16
// speedup vs baseline: 1.3543x; 1.3543x over previous
#include <cuda_runtime.h>
#include <cuda_fp16.h>
#include <stdint.h>
#include <math.h>

#define B_ 8
#define T_ 2048
#define D_ 512
#define NH_ 8
#define DH_ 64
#define L_ 4
#define UP_ 704
#define EPS_ 1e-5f
#define NTOK_ (B_*T_)

// ---------------- static device scratch (no allocation allowed) -------------
__device__ float g_x [(size_t)NTOK_*D_];
__device__ float g_xn[(size_t)NTOK_*D_];
__device__ float g_xc[(size_t)NTOK_*D_];
__device__ float g_gates[(size_t)T_*B_*NH_*4*DH_];
__device__ float g_h [(size_t)NTOK_*D_];
__device__ float g_ge[(size_t)NTOK_*UP_];
__device__ float g_wui[(size_t)L_*D_*2*UP_];   // interleaved w_up copy

// ---------------- packed helpers ----------------------------------------------
#define FMA2(acc,xx,yy) asm("fma.rn.f32x2 %0,%1,%2,%0;" : "+l"(acc) : "l"(xx),"l"(yy))
#define PACK2(d,s)      asm("mov.b64 %0, {%1,%1};" : "=l"(d) : "f"(s))
#define UNPK2(lo,hi,p)  asm("mov.b64 {%0,%1},%2;" : "=f"(lo),"=f"(hi) : "l"(p))
__device__ __forceinline__ float sum2(unsigned long long p){
    float a,b; asm("mov.b64 {%0,%1},%2;" : "=f"(a),"=f"(b) : "l"(p)); return a+b;
}
__device__ __forceinline__ uint32_t f2h2(float lo, float hi){
    uint32_t r; asm("cvt.rn.f16x2.f32 %0, %1, %2;" : "=r"(r) : "f"(hi), "f"(lo)); return r;
}
__device__ __forceinline__ uint32_t smem_u32(const void* p){
    uint32_t a; asm("{ .reg .u64 t; cvta.to.shared.u64 t, %1; cvt.u32.u64 %0, t; }"
                    : "=r"(a) : "l"(p));
    return a;
}
__device__ __forceinline__ void ldsm4(uint32_t& r0,uint32_t& r1,uint32_t& r2,uint32_t& r3,
                                      uint32_t addr){
    asm volatile("ldmatrix.sync.aligned.m8n8.x4.shared.b16 {%0,%1,%2,%3}, [%4];"
        : "=r"(r0),"=r"(r1),"=r"(r2),"=r"(r3) : "r"(addr));
}
__device__ __forceinline__ void mma16(float* c, uint32_t a0,uint32_t a1,uint32_t a2,uint32_t a3,
                                      uint32_t b0,uint32_t b1){
    asm volatile("mma.sync.aligned.m16n8k16.row.col.f32.f16.f16.f32 "
                 "{%0,%1,%2,%3},{%4,%5,%6,%7},{%8,%9},{%0,%1,%2,%3};\n"
                 : "+f"(c[0]),"+f"(c[1]),"+f"(c[2]),"+f"(c[3])
                 : "r"(a0),"r"(a1),"r"(a2),"r"(a3),"r"(b0),"r"(b1));
}
__device__ __forceinline__ float gelu_f(float x){
    return 0.5f*x*(1.f+erff(x*0.70710678118654752f));
}

// named barriers for the scan's producer/consumer split (128-thread block)
__device__ __forceinline__ void bar_sync1()  { asm volatile("bar.sync 1, 128;"   ::: "memory"); }
__device__ __forceinline__ void bar_arrive1(){ asm volatile("bar.arrive 1, 128;" ::: "memory"); }
__device__ __forceinline__ void bar_sync2()  { asm volatile("bar.sync 2, 128;"   ::: "memory"); }

// ------- w_up column interleave: dst[..][c'] = src[..][c] ---------------------
__global__ void k_ilv(const float* __restrict__ src, float* __restrict__ dst){
    size_t i = (size_t)blockIdx.x*256 + threadIdx.x;
    int c = (int)(i % (2*UP_));
    size_t rl = i / (2*UP_);
    int cr = (c < UP_) ? 2*c : 2*(c-UP_)+1;
    dst[rl*(2*UP_) + cr] = src[i];
}

// ---------------- elementwise kernels ----------------------------------------
__global__ void k_mask(const float* __restrict__ x, const unsigned char* __restrict__ mask,
                       float* __restrict__ out){
    int i = blockIdx.x*256 + threadIdx.x;
    float4 v = ((const float4*)x)[i];
    if (mask[i>>7]) { v.x=0.f; v.y=0.f; v.z=0.f; v.w=0.f; }
    ((float4*)out)[i] = v;
}

__global__ void k_ln(const float* __restrict__ in, const float* __restrict__ w,
                     float* __restrict__ out){
    int tok = blockIdx.x, tid = threadIdx.x;
    float4 v = ((const float4*)(in + (size_t)tok*D_))[tid];
    float s  = v.x+v.y+v.z+v.w;
    float sq = v.x*v.x+v.y*v.y+v.z*v.z+v.w*v.w;
    #pragma unroll
    for (int o=16;o>0;o>>=1){ s += __shfl_xor_sync(0xffffffffu,s,o); sq += __shfl_xor_sync(0xffffffffu,sq,o); }
    __shared__ float sb[8];
    int warp=tid>>5, lane=tid&31;
    if (lane==0){ sb[warp]=s; sb[4+warp]=sq; }
    __syncthreads();
    s  = sb[0]+sb[1]+sb[2]+sb[3];
    sq = sb[4]+sb[5]+sb[6]+sb[7];
    float mu  = s*(1.f/(float)D_);
    float var = sq*(1.f/(float)D_) - mu*mu;
    float r = rsqrtf(var + EPS_);
    float4 wv = ((const float4*)w)[tid];
    float4 o4;
    o4.x=(v.x-mu)*r*wv.x; o4.y=(v.y-mu)*r*wv.y; o4.z=(v.z-mu)*r*wv.z; o4.w=(v.w-mu)*r*wv.w;
    ((float4*)(out + (size_t)tok*D_))[tid] = o4;
}

__global__ void k_conv(const float* __restrict__ xn, const float* __restrict__ cw,
                       const float* __restrict__ cb, float* __restrict__ xc){
    int i = blockIdx.x*256 + threadIdx.x;
    int tok = i >> 7, d4 = i & 127;
    int b = tok >> 11, t = tok & (T_-1);
    float4 bz = ((const float4*)cb)[d4];
    float ax=bz.x, ay=bz.y, az=bz.z, aw=bz.w;
    #pragma unroll
    for (int k=0;k<4;k++){
        int tt = t + k - 3;
        if (tt >= 0){
            float4 xv = ((const float4*)xn)[(size_t)(((b<<11)+tt)*128 + d4)];
            float4 wv = ((const float4*)cw)[k*128 + d4];
            ax = fmaf(xv.x, wv.x, ax); ay = fmaf(xv.y, wv.y, ay);
            az = fmaf(xv.z, wv.z, az); aw = fmaf(xv.w, wv.w, aw);
        }
    }
    float4 o;
    o.x = ax/(1.f+__expf(-ax));
    o.y = ay/(1.f+__expf(-ay));
    o.z = az/(1.f+__expf(-az));
    o.w = aw/(1.f+__expf(-aw));
    ((float4*)xc)[i] = o;
}

// ------- fused GroupNorm + residual + LayerNorm(ln2) -> fp32 xn ---------------
__global__ void __launch_bounds__(256) k_gnres_ln(const float* __restrict__ h,
    const float* __restrict__ gnw, float* __restrict__ x,
    const float* __restrict__ w2, float* __restrict__ xn)
{
    int tok = blockIdx.x;
    int warp = threadIdx.x>>5, lane = threadIdx.x&31;
    const float2* hp = (const float2*)(h + (size_t)tok*D_ + warp*DH_);
    float2 v = hp[lane];
    float s = v.x+v.y, sq = v.x*v.x+v.y*v.y;
    #pragma unroll
    for (int o=16;o>0;o>>=1){ s += __shfl_xor_sync(0xffffffffu,s,o); sq += __shfl_xor_sync(0xffffffffu,sq,o); }
    float mu = s*(1.f/(float)DH_);
    float var = sq*(1.f/(float)DH_) - mu*mu;
    float r = rsqrtf(var + EPS_);
    float2 gw = ((const float2*)(gnw + warp*DH_))[lane];
    float2* xp = (float2*)(x + (size_t)tok*D_ + warp*DH_);
    float2 xv = xp[lane];
    xv.x += (v.x-mu)*r*gw.x;
    xv.y += (v.y-mu)*r*gw.y;
    xp[lane] = xv;

    float s2 = xv.x+xv.y, q2 = xv.x*xv.x+xv.y*xv.y;
    #pragma unroll
    for (int o=16;o>0;o>>=1){ s2 += __shfl_xor_sync(0xffffffffu,s2,o); q2 += __shfl_xor_sync(0xffffffffu,q2,o); }
    __shared__ float sb[16];
    if (lane==0){ sb[warp]=s2; sb[8+warp]=q2; }
    __syncthreads();
    s2 = sb[0]+sb[1]+sb[2]+sb[3]+sb[4]+sb[5]+sb[6]+sb[7];
    q2 = sb[8]+sb[9]+sb[10]+sb[11]+sb[12]+sb[13]+sb[14]+sb[15];
    float mu2  = s2*(1.f/(float)D_);
    float var2 = q2*(1.f/(float)D_) - mu2*mu2;
    float r2 = rsqrtf(var2 + EPS_);
    float2 lw = ((const float2*)(w2 + warp*DH_))[lane];
    float2 o2;
    o2.x = (xv.x-mu2)*r2*lw.x;
    o2.y = (xv.y-mu2)*r2*lw.y;
    ((float2*)(xn + (size_t)tok*D_ + warp*DH_))[lane] = o2;
}

// ------- gate projections: register-tiled fp32 GEMM (unchanged) --------------
__global__ void __launch_bounds__(256) k_gates(const float* __restrict__ xc,
    const float* __restrict__ xn, const float* __restrict__ Wg_l,
    const float* __restrict__ bg_l, float* __restrict__ gates)
{
    __shared__ float in_t[64][64];
    __shared__ float w_s[64][128];
    const int tok0 = blockIdx.x * 64;
    const int h    = blockIdx.y;
    const int z    = blockIdx.z;
    const int tid  = threadIdx.x;
    const float* src = z ? xn : xc;

    {
        const int tok_l = tid >> 2;
        const int kq    = (tid & 3) * 16;
        const float* sp = src + (size_t)(tok0+tok_l)*D_ + h*64 + kq;
        #pragma unroll
        for (int j=0;j<4;j++){
            float4 v = *(const float4*)(sp + j*4);
            in_t[kq+j*4+0][tok_l] = v.x;
            in_t[kq+j*4+1][tok_l] = v.y;
            in_t[kq+j*4+2][tok_l] = v.z;
            in_t[kq+j*4+3][tok_l] = v.w;
        }
    }
    {
        const int r   = tid >> 1;
        const int kq2 = (tid & 1) * 32;
        const float* wrow = Wg_l + ((size_t)((2*z + (r>>6))*NH_ + h)*64 + (r&63))*64 + kq2;
        #pragma unroll
        for (int j=0;j<8;j++){
            float4 v = *(const float4*)(wrow + j*4);
            w_s[kq2+j*4+0][r] = v.x;
            w_s[kq2+j*4+1][r] = v.y;
            w_s[kq2+j*4+2][r] = v.z;
            w_s[kq2+j*4+3][r] = v.w;
        }
    }
    __syncthreads();

    const int tok0t = (tid >> 5) * 8;
    const int o0    = (tid & 31) * 4;

    unsigned long long acc[16];
    #pragma unroll
    for (int i=0;i<16;i++) acc[i] = 0ull;

    #pragma unroll 16
    for (int k=0;k<64;k++){
        ulonglong2 iA = *(const ulonglong2*)&in_t[k][tok0t];
        ulonglong2 iB = *(const ulonglong2*)&in_t[k][tok0t+4];
        float4 wv = *(const float4*)&w_s[k][o0];
        unsigned long long w0,w1,w2,w3;
        PACK2(w0,wv.x); PACK2(w1,wv.y); PACK2(w2,wv.z); PACK2(w3,wv.w);
        FMA2(acc[ 0], iA.x, w0); FMA2(acc[ 1], iA.x, w1); FMA2(acc[ 2], iA.x, w2); FMA2(acc[ 3], iA.x, w3);
        FMA2(acc[ 4], iA.y, w0); FMA2(acc[ 5], iA.y, w1); FMA2(acc[ 6], iA.y, w2); FMA2(acc[ 7], iA.y, w3);
        FMA2(acc[ 8], iB.x, w0); FMA2(acc[ 9], iB.x, w1); FMA2(acc[10], iB.x, w2); FMA2(acc[11], iB.x, w3);
        FMA2(acc[12], iB.y, w0); FMA2(acc[13], iB.y, w1); FMA2(acc[14], iB.y, w2); FMA2(acc[15], iB.y, w3);
    }

    float4 bias = *(const float4*)(bg_l + (size_t)((2*z + (o0>>6))*NH_ + h)*64 + (o0&63));
    #pragma unroll
    for (int p=0;p<4;p++){
        float lo0,hi0,lo1,hi1,lo2,hi2,lo3,hi3;
        UNPK2(lo0,hi0,acc[p*4+0]);
        UNPK2(lo1,hi1,acc[p*4+1]);
        UNPK2(lo2,hi2,acc[p*4+2]);
        UNPK2(lo3,hi3,acc[p*4+3]);
        #pragma unroll
        for (int half=0;half<2;half++){
            int tok = tok0 + tok0t + p*2 + half;
            int bb = tok >> 11, tt = tok & (T_-1);
            float4 o4;
            o4.x = (half ? hi0 : lo0) + bias.x;
            o4.y = (half ? hi1 : lo1) + bias.y;
            o4.z = (half ? hi2 : lo2) + bias.z;
            o4.w = (half ? hi3 : lo3) + bias.w;
            *(float4*)(gates + (((size_t)tt*B_+bb)*NH_+h)*256 + z*128 + o0) = o4;
        }
    }
}

// ------- sLSTM scan: 128 threads, 2 outputs/thread (h loaded once) -----------
__device__ __forceinline__ float scan_update(float ip_, float fp_, float zp_, float op_,
                                             float& c, float& n, float& m){
    float en   = __expf(-fp_);
    float sinv = 1.f + en;
    float a    = __expf(ip_ - m);
    float w    = a * sinv;
    bool  p    = (w >= 1.f);
    float iv   = p ? 1.f : w;
    float fv   = p ? __fdividef(1.f, w) : 1.f;
    m = p ? ip_ : (m - __logf(sinv));
    float tz = 1.f - __fdividef(2.f, 1.f + __expf(2.f*zp_));
    c = fv*c + iv*tz;
    n = fv*n + iv;
    return __fdividef(c, n + n*__expf(-op_));
}

__global__ void __launch_bounds__(128) k_scan(const float* __restrict__ Rg_l,
    const float* __restrict__ gates, float* __restrict__ hout)
{
    const int b = blockIdx.x >> 3, h = blockIdx.x & 7;
    const int tid = threadIdx.x, g0 = tid >> 6, e = tid & 63;
    __shared__ __align__(16) float h_sm[64];
    __shared__ float gsm[256];
    // two R rows per thread: (g0, e) and (g0+2, e)
    unsigned long long Rp0[32], Rp1[32];
    {
        const ulonglong2* R0 = (const ulonglong2*)(Rg_l + ((size_t)( g0   *NH_+h)*64 + e)*64);
        const ulonglong2* R1 = (const ulonglong2*)(Rg_l + ((size_t)((g0+2)*NH_+h)*64 + e)*64);
        #pragma unroll
        for (int i=0;i<16;i++){
            ulonglong2 w0 = R0[i]; Rp0[2*i]=w0.x; Rp0[2*i+1]=w0.y;
            ulonglong2 w1 = R1[i]; Rp1[2*i]=w1.x; Rp1[2*i+1]=w1.y;
        }
    }
    if (tid < 64) h_sm[tid] = 0.f;
    float c=0.f, n=0.f, m=0.f;
    const float* gbase = gates + ((size_t)b*NH_+h)*256;
    const size_t tstride = (size_t)B_*NH_*256;

    float gbuf0[8], gbuf1[8];
    #pragma unroll
    for (int q=0;q<8;q++){
        gbuf0[q] = __ldg(gbase + (size_t)q*tstride + tid);
        gbuf1[q] = __ldg(gbase + (size_t)q*tstride + 128 + tid);
    }
    __syncthreads();

    float* hbase = hout + (size_t)b*T_*D_ + h*DH_ + tid;  // used by tid<64

    for (int t=0; t<T_; t+=8){
        #pragma unroll
        for (int q=0;q<8;q++){
            float gp0 = gbuf0[q], gp1 = gbuf1[q];
            if (t+q+8 < T_){
                gbuf0[q] = __ldg(gbase + (size_t)(t+q+8)*tstride + tid);
                gbuf1[q] = __ldg(gbase + (size_t)(t+q+8)*tstride + 128 + tid);
            }
            unsigned long long a0[4] = {0ull,0ull,0ull,0ull};
            unsigned long long a1[4] = {0ull,0ull,0ull,0ull};
            const ulonglong2* hp = (const ulonglong2*)h_sm;
            #pragma unroll
            for (int j=0;j<16;j++){
                ulonglong2 hv = hp[j];
                FMA2(a0[j&1],     Rp0[2*j],   hv.x);
                FMA2(a0[2+(j&1)], Rp0[2*j+1], hv.y);
                FMA2(a1[j&1],     Rp1[2*j],   hv.x);
                FMA2(a1[2+(j&1)], Rp1[2*j+1], hv.y);
            }
            gsm[tid]     = sum2(a0[0])+sum2(a0[1])+sum2(a0[2])+sum2(a0[3]) + gp0;
            gsm[128+tid] = sum2(a1[0])+sum2(a1[1])+sum2(a1[2])+sum2(a1[3]) + gp1;
            if (tid >= 64){
                bar_arrive1();
                bar_sync2();
            } else {
                bar_sync1();
                float ip_ = gsm[tid], fp_ = gsm[64+tid], zp_ = gsm[128+tid], op_ = gsm[192+tid];
                float hv = scan_update(ip_, fp_, zp_, op_, c, n, m);
                h_sm[tid] = hv;
                hbase[(size_t)(t+q)*D_] = hv;
                bar_sync2();
            }
        }
    }
}

// ------- fp16 tensor-core GEMM (fp32 staging) + LDSM fragments + fused epi ----
// mode 0: C = A*B    mode 1: Cge = gelu/up pairs (interleaved N)   mode 2: C += A*B
#define KW 20
__global__ void __launch_bounds__(256) k_gemm16(const float* __restrict__ A,
    const float* __restrict__ Bm, float* __restrict__ C, float* __restrict__ Cge,
    int N, int K, int mode)
{
    __shared__ uint32_t As[2][128*KW];
    __shared__ uint32_t Bs[2][128*KW];
    const int m0 = blockIdx.x*128, n0 = blockIdx.y*128;
    const int tid = threadIdx.x;
    const int warp=tid>>5, lane=tid&31, gid=lane>>2, tig=lane&3;
    const int wm=(warp&3)*32, wn=(warp>>2)*64;
    float acc[16][4];
    #pragma unroll
    for (int i=0;i<16;i++){ acc[i][0]=0.f; acc[i][1]=0.f; acc[i][2]=0.f; acc[i][3]=0.f; }

    const int ar  = tid>>3;
    const int ac4 = tid&7;
    const int bn  = tid&127;
    const int bkh = (tid>>7)*16;

    const int rowsel = (lane & 7) + (lane & 8);
    const int colsel = (lane & 16) ? 4 : 0;
    const uint32_t as_base = smem_u32(&As[0][0]);
    const uint32_t bs_base = smem_u32(&Bs[0][0]);

    float4 ra[4]; float rb[16];

    #pragma unroll
    for (int j=0;j<4;j++) ra[j] = *(const float4*)(A + (size_t)(m0+ar+j*32)*K + ac4*4);
    {
        const float* bp = Bm + (size_t)bkh*N + n0 + bn;
        #pragma unroll
        for (int j=0;j<16;j++) rb[j] = bp[(size_t)j*N];
    }
    #pragma unroll
    for (int j=0;j<4;j++){
        uint32_t* dst = &As[0][(ar+j*32)*KW + ac4*2];
        dst[0] = f2h2(ra[j].x, ra[j].y);
        dst[1] = f2h2(ra[j].z, ra[j].w);
    }
    #pragma unroll
    for (int w=0;w<8;w++) Bs[0][bn*KW + (bkh>>1) + w] = f2h2(rb[2*w], rb[2*w+1]);
    __syncthreads();

    const int nk = K >> 5;
    for (int i=0; i<nk; i++){
        const int cur = i&1;
        if (i+1 < nk){
            const int kb = (i+1)*32;
            #pragma unroll
            for (int j=0;j<4;j++) ra[j] = *(const float4*)(A + (size_t)(m0+ar+j*32)*K + kb + ac4*4);
            const float* bp = Bm + (size_t)(kb+bkh)*N + n0 + bn;
            #pragma unroll
            for (int j=0;j<16;j++) rb[j] = bp[(size_t)j*N];
        }
        const uint32_t abuf = as_base + (uint32_t)cur*(128*KW*4);
        const uint32_t bbuf = bs_base + (uint32_t)cur*(128*KW*4);
        #pragma unroll
        for (int ks=0;ks<2;ks++){
            const int k0w = ks*8;
            uint32_t a[2][4];
            #pragma unroll
            for (int mt=0;mt<2;mt++){
                uint32_t addr = abuf + ((wm + mt*16 + rowsel)*KW + k0w + colsel)*4;
                ldsm4(a[mt][0], a[mt][1], a[mt][2], a[mt][3], addr);
            }
            #pragma unroll
            for (int ntp=0;ntp<4;ntp++){
                uint32_t b0e,b0o,b1e,b1o;
                uint32_t addr = bbuf + ((wn + ntp*16 + rowsel)*KW + k0w + colsel)*4;
                ldsm4(b0e, b0o, b1e, b1o, addr);
                const int nt = 2*ntp;
                mma16(acc[nt],     a[0][0],a[0][1],a[0][2],a[0][3], b0e,b1e);
                mma16(acc[8+nt],   a[1][0],a[1][1],a[1][2],a[1][3], b0e,b1e);
                mma16(acc[nt+1],   a[0][0],a[0][1],a[0][2],a[0][3], b0o,b1o);
                mma16(acc[8+nt+1], a[1][0],a[1][1],a[1][2],a[1][3], b0o,b1o);
            }
        }
        if (i+1 < nk){
            const int nxt = cur^1;
            #pragma unroll
            for (int j=0;j<4;j++){
                uint32_t* dst = &As[nxt][(ar+j*32)*KW + ac4*2];
                dst[0] = f2h2(ra[j].x, ra[j].y);
                dst[1] = f2h2(ra[j].z, ra[j].w);
            }
            #pragma unroll
            for (int w=0;w<8;w++) Bs[nxt][bn*KW + (bkh>>1) + w] = f2h2(rb[2*w], rb[2*w+1]);
        }
        __syncthreads();
    }

    if (mode == 1){
        #pragma unroll
        for (int mt=0;mt<2;mt++)
          #pragma unroll
          for (int nt=0;nt<8;nt++){
            int r    = m0 + wm + mt*16 + gid;
            int cidx = n0 + wn + nt*8 + tig*2;
            int j    = cidx >> 1;
            const float* a4 = acc[mt*8+nt];
            Cge[(size_t)r*UP_ + j]     = gelu_f(a4[0]) * a4[1];
            Cge[(size_t)(r+8)*UP_ + j] = gelu_f(a4[2]) * a4[3];
          }
    } else {
        #pragma unroll
        for (int mt=0;mt<2;mt++)
          #pragma unroll
          for (int nt=0;nt<8;nt++){
            int r    = m0 + wm + mt*16 + gid;
            int cidx = n0 + wn + nt*8 + tig*2;
            float* p0 = C + (size_t)r*N + cidx;
            float* p1 = C + (size_t)(r+8)*N + cidx;
            const float* a4 = acc[mt*8+nt];
            if (mode == 2){
                p0[0]+=a4[0]; p0[1]+=a4[1];
                p1[0]+=a4[2]; p1[1]+=a4[3];
            } else {
                p0[0]=a4[0]; p0[1]=a4[1];
                p1[0]=a4[2]; p1[1]=a4[3];
            }
          }
    }
}

// ---------------- launch ------------------------------------------------------
extern "C" void kernel_launch(void* const* d_in, const int* in_sizes, int n_in,
                              void* d_out, int out_size) {
    const float* x        = (const float*)d_in[0];
    const unsigned char* mask = (const unsigned char*)d_in[1];
    const float* ln1_w    = (const float*)d_in[2];
    const float* conv_w   = (const float*)d_in[3];
    const float* conv_b   = (const float*)d_in[4];
    const float* Wg       = (const float*)d_in[5];
    const float* Rg       = (const float*)d_in[6];
    const float* bg       = (const float*)d_in[7];
    const float* gn_w     = (const float*)d_in[8];
    const float* ln2_w    = (const float*)d_in[9];
    const float* w_up     = (const float*)d_in[10];
    const float* w_down   = (const float*)d_in[11];
    const float* post_ln  = (const float*)d_in[12];
    float* out = (float*)d_out;

    float *px,*pxn,*pxc,*pg,*ph,*pge,*pwui;
    cudaGetSymbolAddress((void**)&px,  g_x);
    cudaGetSymbolAddress((void**)&pxn, g_xn);
    cudaGetSymbolAddress((void**)&pxc, g_xc);
    cudaGetSymbolAddress((void**)&pg,  g_gates);
    cudaGetSymbolAddress((void**)&ph,  g_h);
    cudaGetSymbolAddress((void**)&pge, g_ge);
    cudaGetSymbolAddress((void**)&pwui, g_wui);

    k_ilv<<<(L_*D_*2*UP_)/256, 256>>>(w_up, pwui);

    k_mask<<<NTOK_*128/256, 256>>>(x, mask, px);
    for (int l=0; l<L_; l++){
        k_ln<<<NTOK_,128>>>(px, ln1_w + l*D_, pxn);
        k_conv<<<NTOK_*128/256,256>>>(pxn, conv_w + l*4*D_, conv_b + l*D_, pxc);
        dim3 gg(NTOK_/64, NH_, 2);
        k_gates<<<gg,256>>>(pxc, pxn, Wg + (size_t)l*4*NH_*DH_*DH_, bg + l*4*NH_*DH_, pg);
        k_scan<<<64,128>>>(Rg + (size_t)l*4*NH_*DH_*DH_, pg, ph);
        k_gnres_ln<<<NTOK_,256>>>(ph, gn_w + l*D_, px, ln2_w + l*D_, pxn);
        dim3 gu(NTOK_/128, (2*UP_)/128);
        k_gemm16<<<gu,256>>>(pxn, pwui + (size_t)l*D_*2*UP_, nullptr, pge, 2*UP_, D_, 1);
        dim3 gd(NTOK_/128, D_/128);
        k_gemm16<<<gd,256>>>(pge, w_down + (size_t)l*UP_*D_, px, nullptr, D_, UP_, 2);
    }
    k_ln<<<NTOK_,128>>>(px, post_ln, out);
}

// round 17
// speedup vs baseline: 1.4158x; 1.0454x over previous
#include <cuda_runtime.h>
#include <cuda_fp16.h>
#include <stdint.h>
#include <math.h>

#define B_ 8
#define T_ 2048
#define D_ 512
#define NH_ 8
#define DH_ 64
#define L_ 4
#define UP_ 704
#define EPS_ 1e-5f
#define NTOK_ (B_*T_)

// ---------------- static device scratch (no allocation allowed) -------------
__device__ float g_x [(size_t)NTOK_*D_];
__device__ float g_xn[(size_t)NTOK_*D_];
__device__ float g_xc[(size_t)NTOK_*D_];
__device__ float g_gates[(size_t)T_*B_*NH_*4*DH_];
__device__ float g_h [(size_t)NTOK_*D_];
__device__ float g_ge[(size_t)NTOK_*UP_];
__device__ float g_wui[(size_t)L_*D_*2*UP_];   // interleaved w_up copy

// ---------------- packed helpers ----------------------------------------------
#define FMA2(acc,xx,yy) asm("fma.rn.f32x2 %0,%1,%2,%0;" : "+l"(acc) : "l"(xx),"l"(yy))
#define PACK2(d,s)      asm("mov.b64 %0, {%1,%1};" : "=l"(d) : "f"(s))
#define UNPK2(lo,hi,p)  asm("mov.b64 {%0,%1},%2;" : "=f"(lo),"=f"(hi) : "l"(p))
__device__ __forceinline__ float sum2(unsigned long long p){
    float a,b; asm("mov.b64 {%0,%1},%2;" : "=f"(a),"=f"(b) : "l"(p)); return a+b;
}
__device__ __forceinline__ uint32_t f2h2(float lo, float hi){
    uint32_t r; asm("cvt.rn.f16x2.f32 %0, %1, %2;" : "=r"(r) : "f"(hi), "f"(lo)); return r;
}
__device__ __forceinline__ uint32_t smem_u32(const void* p){
    uint32_t a; asm("{ .reg .u64 t; cvta.to.shared.u64 t, %1; cvt.u32.u64 %0, t; }"
                    : "=r"(a) : "l"(p));
    return a;
}
__device__ __forceinline__ void ldsm4(uint32_t& r0,uint32_t& r1,uint32_t& r2,uint32_t& r3,
                                      uint32_t addr){
    asm volatile("ldmatrix.sync.aligned.m8n8.x4.shared.b16 {%0,%1,%2,%3}, [%4];"
        : "=r"(r0),"=r"(r1),"=r"(r2),"=r"(r3) : "r"(addr));
}
__device__ __forceinline__ void mma16(float* c, uint32_t a0,uint32_t a1,uint32_t a2,uint32_t a3,
                                      uint32_t b0,uint32_t b1){
    asm volatile("mma.sync.aligned.m16n8k16.row.col.f32.f16.f16.f32 "
                 "{%0,%1,%2,%3},{%4,%5,%6,%7},{%8,%9},{%0,%1,%2,%3};\n"
                 : "+f"(c[0]),"+f"(c[1]),"+f"(c[2]),"+f"(c[3])
                 : "r"(a0),"r"(a1),"r"(a2),"r"(a3),"r"(b0),"r"(b1));
}
__device__ __forceinline__ float gelu_f(float x){
    return 0.5f*x*(1.f+erff(x*0.70710678118654752f));
}

// ------- w_up column interleave: dst[..][c'] = src[..][c] ---------------------
__global__ void k_ilv(const float* __restrict__ src, float* __restrict__ dst){
    size_t i = (size_t)blockIdx.x*256 + threadIdx.x;
    int c = (int)(i % (2*UP_));
    size_t rl = i / (2*UP_);
    int cr = (c < UP_) ? 2*c : 2*(c-UP_)+1;
    dst[rl*(2*UP_) + cr] = src[i];
}

// ---------------- elementwise kernels ----------------------------------------
__global__ void k_mask(const float* __restrict__ x, const unsigned char* __restrict__ mask,
                       float* __restrict__ out){
    int i = blockIdx.x*256 + threadIdx.x;
    float4 v = ((const float4*)x)[i];
    if (mask[i>>7]) { v.x=0.f; v.y=0.f; v.z=0.f; v.w=0.f; }
    ((float4*)out)[i] = v;
}

__global__ void k_ln(const float* __restrict__ in, const float* __restrict__ w,
                     float* __restrict__ out){
    int tok = blockIdx.x, tid = threadIdx.x;
    float4 v = ((const float4*)(in + (size_t)tok*D_))[tid];
    float s  = v.x+v.y+v.z+v.w;
    float sq = v.x*v.x+v.y*v.y+v.z*v.z+v.w*v.w;
    #pragma unroll
    for (int o=16;o>0;o>>=1){ s += __shfl_xor_sync(0xffffffffu,s,o); sq += __shfl_xor_sync(0xffffffffu,sq,o); }
    __shared__ float sb[8];
    int warp=tid>>5, lane=tid&31;
    if (lane==0){ sb[warp]=s; sb[4+warp]=sq; }
    __syncthreads();
    s  = sb[0]+sb[1]+sb[2]+sb[3];
    sq = sb[4]+sb[5]+sb[6]+sb[7];
    float mu  = s*(1.f/(float)D_);
    float var = sq*(1.f/(float)D_) - mu*mu;
    float r = rsqrtf(var + EPS_);
    float4 wv = ((const float4*)w)[tid];
    float4 o4;
    o4.x=(v.x-mu)*r*wv.x; o4.y=(v.y-mu)*r*wv.y; o4.z=(v.z-mu)*r*wv.z; o4.w=(v.w-mu)*r*wv.w;
    ((float4*)(out + (size_t)tok*D_))[tid] = o4;
}

__global__ void k_conv(const float* __restrict__ xn, const float* __restrict__ cw,
                       const float* __restrict__ cb, float* __restrict__ xc){
    int i = blockIdx.x*256 + threadIdx.x;
    int tok = i >> 7, d4 = i & 127;
    int b = tok >> 11, t = tok & (T_-1);
    float4 bz = ((const float4*)cb)[d4];
    float ax=bz.x, ay=bz.y, az=bz.z, aw=bz.w;
    #pragma unroll
    for (int k=0;k<4;k++){
        int tt = t + k - 3;
        if (tt >= 0){
            float4 xv = ((const float4*)xn)[(size_t)(((b<<11)+tt)*128 + d4)];
            float4 wv = ((const float4*)cw)[k*128 + d4];
            ax = fmaf(xv.x, wv.x, ax); ay = fmaf(xv.y, wv.y, ay);
            az = fmaf(xv.z, wv.z, az); aw = fmaf(xv.w, wv.w, aw);
        }
    }
    float4 o;
    o.x = ax/(1.f+__expf(-ax));
    o.y = ay/(1.f+__expf(-ay));
    o.z = az/(1.f+__expf(-az));
    o.w = aw/(1.f+__expf(-aw));
    ((float4*)xc)[i] = o;
}

// ------- fused GroupNorm + residual + LayerNorm(ln2) -> fp32 xn ---------------
__global__ void __launch_bounds__(256) k_gnres_ln(const float* __restrict__ h,
    const float* __restrict__ gnw, float* __restrict__ x,
    const float* __restrict__ w2, float* __restrict__ xn)
{
    int tok = blockIdx.x;
    int warp = threadIdx.x>>5, lane = threadIdx.x&31;
    const float2* hp = (const float2*)(h + (size_t)tok*D_ + warp*DH_);
    float2 v = hp[lane];
    float s = v.x+v.y, sq = v.x*v.x+v.y*v.y;
    #pragma unroll
    for (int o=16;o>0;o>>=1){ s += __shfl_xor_sync(0xffffffffu,s,o); sq += __shfl_xor_sync(0xffffffffu,sq,o); }
    float mu = s*(1.f/(float)DH_);
    float var = sq*(1.f/(float)DH_) - mu*mu;
    float r = rsqrtf(var + EPS_);
    float2 gw = ((const float2*)(gnw + warp*DH_))[lane];
    float2* xp = (float2*)(x + (size_t)tok*D_ + warp*DH_);
    float2 xv = xp[lane];
    xv.x += (v.x-mu)*r*gw.x;
    xv.y += (v.y-mu)*r*gw.y;
    xp[lane] = xv;

    float s2 = xv.x+xv.y, q2 = xv.x*xv.x+xv.y*xv.y;
    #pragma unroll
    for (int o=16;o>0;o>>=1){ s2 += __shfl_xor_sync(0xffffffffu,s2,o); q2 += __shfl_xor_sync(0xffffffffu,q2,o); }
    __shared__ float sb[16];
    if (lane==0){ sb[warp]=s2; sb[8+warp]=q2; }
    __syncthreads();
    s2 = sb[0]+sb[1]+sb[2]+sb[3]+sb[4]+sb[5]+sb[6]+sb[7];
    q2 = sb[8]+sb[9]+sb[10]+sb[11]+sb[12]+sb[13]+sb[14]+sb[15];
    float mu2  = s2*(1.f/(float)D_);
    float var2 = q2*(1.f/(float)D_) - mu2*mu2;
    float r2 = rsqrtf(var2 + EPS_);
    float2 lw = ((const float2*)(w2 + warp*DH_))[lane];
    float2 o2;
    o2.x = (xv.x-mu2)*r2*lw.x;
    o2.y = (xv.y-mu2)*r2*lw.y;
    ((float2*)(xn + (size_t)tok*D_ + warp*DH_))[lane] = o2;
}

// ------- gate projections: register-tiled fp32 GEMM (unchanged) --------------
__global__ void __launch_bounds__(256) k_gates(const float* __restrict__ xc,
    const float* __restrict__ xn, const float* __restrict__ Wg_l,
    const float* __restrict__ bg_l, float* __restrict__ gates)
{
    __shared__ float in_t[64][64];
    __shared__ float w_s[64][128];
    const int tok0 = blockIdx.x * 64;
    const int h    = blockIdx.y;
    const int z    = blockIdx.z;
    const int tid  = threadIdx.x;
    const float* src = z ? xn : xc;

    {
        const int tok_l = tid >> 2;
        const int kq    = (tid & 3) * 16;
        const float* sp = src + (size_t)(tok0+tok_l)*D_ + h*64 + kq;
        #pragma unroll
        for (int j=0;j<4;j++){
            float4 v = *(const float4*)(sp + j*4);
            in_t[kq+j*4+0][tok_l] = v.x;
            in_t[kq+j*4+1][tok_l] = v.y;
            in_t[kq+j*4+2][tok_l] = v.z;
            in_t[kq+j*4+3][tok_l] = v.w;
        }
    }
    {
        const int r   = tid >> 1;
        const int kq2 = (tid & 1) * 32;
        const float* wrow = Wg_l + ((size_t)((2*z + (r>>6))*NH_ + h)*64 + (r&63))*64 + kq2;
        #pragma unroll
        for (int j=0;j<8;j++){
            float4 v = *(const float4*)(wrow + j*4);
            w_s[kq2+j*4+0][r] = v.x;
            w_s[kq2+j*4+1][r] = v.y;
            w_s[kq2+j*4+2][r] = v.z;
            w_s[kq2+j*4+3][r] = v.w;
        }
    }
    __syncthreads();

    const int tok0t = (tid >> 5) * 8;
    const int o0    = (tid & 31) * 4;

    unsigned long long acc[16];
    #pragma unroll
    for (int i=0;i<16;i++) acc[i] = 0ull;

    #pragma unroll 16
    for (int k=0;k<64;k++){
        ulonglong2 iA = *(const ulonglong2*)&in_t[k][tok0t];
        ulonglong2 iB = *(const ulonglong2*)&in_t[k][tok0t+4];
        float4 wv = *(const float4*)&w_s[k][o0];
        unsigned long long w0,w1,w2,w3;
        PACK2(w0,wv.x); PACK2(w1,wv.y); PACK2(w2,wv.z); PACK2(w3,wv.w);
        FMA2(acc[ 0], iA.x, w0); FMA2(acc[ 1], iA.x, w1); FMA2(acc[ 2], iA.x, w2); FMA2(acc[ 3], iA.x, w3);
        FMA2(acc[ 4], iA.y, w0); FMA2(acc[ 5], iA.y, w1); FMA2(acc[ 6], iA.y, w2); FMA2(acc[ 7], iA.y, w3);
        FMA2(acc[ 8], iB.x, w0); FMA2(acc[ 9], iB.x, w1); FMA2(acc[10], iB.x, w2); FMA2(acc[11], iB.x, w3);
        FMA2(acc[12], iB.y, w0); FMA2(acc[13], iB.y, w1); FMA2(acc[14], iB.y, w2); FMA2(acc[15], iB.y, w3);
    }

    float4 bias = *(const float4*)(bg_l + (size_t)((2*z + (o0>>6))*NH_ + h)*64 + (o0&63));
    #pragma unroll
    for (int p=0;p<4;p++){
        float lo0,hi0,lo1,hi1,lo2,hi2,lo3,hi3;
        UNPK2(lo0,hi0,acc[p*4+0]);
        UNPK2(lo1,hi1,acc[p*4+1]);
        UNPK2(lo2,hi2,acc[p*4+2]);
        UNPK2(lo3,hi3,acc[p*4+3]);
        #pragma unroll
        for (int half=0;half<2;half++){
            int tok = tok0 + tok0t + p*2 + half;
            int bb = tok >> 11, tt = tok & (T_-1);
            float4 o4;
            o4.x = (half ? hi0 : lo0) + bias.x;
            o4.y = (half ? hi1 : lo1) + bias.y;
            o4.z = (half ? hi2 : lo2) + bias.z;
            o4.w = (half ? hi3 : lo3) + bias.w;
            *(float4*)(gates + (((size_t)tt*B_+bb)*NH_+h)*256 + z*128 + o0) = o4;
        }
    }
}

// ------- sLSTM scan: pair layout, shuffle gate-gather, 1 barrier/step ---------
// tid = e*2 + half. Thread computes gates (half, e) and (half+2, e).
// Element e's four gates live on lanes (2e, 2e+1) of one warp -> shfl gather.
// Update runs pair-redundantly; even lane writes h. Double-buffered h_sm.
__device__ __forceinline__ float scan_update(float ip_, float fp_, float zp_, float op_,
                                             float& c, float& n, float& m){
    float en   = __expf(-fp_);
    float sinv = 1.f + en;
    float a    = __expf(ip_ - m);
    float w    = a * sinv;
    bool  p    = (w >= 1.f);
    float iv   = p ? 1.f : w;
    float fv   = p ? __fdividef(1.f, w) : 1.f;
    m = p ? ip_ : (m - __logf(sinv));
    float tz = 1.f - __fdividef(2.f, 1.f + __expf(2.f*zp_));
    c = fv*c + iv*tz;
    n = fv*n + iv;
    return __fdividef(c, n + n*__expf(-op_));
}

__global__ void __launch_bounds__(128) k_scan(const float* __restrict__ Rg_l,
    const float* __restrict__ gates, float* __restrict__ hout)
{
    const int b = blockIdx.x >> 3, h = blockIdx.x & 7;
    const int tid = threadIdx.x, e = tid >> 1, half = tid & 1;
    const int lane = tid & 31;
    __shared__ __align__(16) float h_sm[2][64];
    unsigned long long Rp0[32], Rp1[32];
    {
        const ulonglong2* R0 = (const ulonglong2*)(Rg_l + ((size_t)( half   *NH_+h)*64 + e)*64);
        const ulonglong2* R1 = (const ulonglong2*)(Rg_l + ((size_t)((half+2)*NH_+h)*64 + e)*64);
        #pragma unroll
        for (int i=0;i<16;i++){
            ulonglong2 w0 = R0[i]; Rp0[2*i]=w0.x; Rp0[2*i+1]=w0.y;
            ulonglong2 w1 = R1[i]; Rp1[2*i]=w1.x; Rp1[2*i+1]=w1.y;
        }
    }
    if (tid < 64) h_sm[0][tid] = 0.f;
    float c=0.f, n=0.f, m=0.f;
    const float* gbase = gates + ((size_t)b*NH_+h)*256;
    const size_t tstride = (size_t)B_*NH_*256;
    const int off0 = half*64 + e;         // gate g = half
    const int off1 = (half+2)*64 + e;     // gate g = half+2

    float gbuf0[8], gbuf1[8];
    #pragma unroll
    for (int q=0;q<8;q++){
        gbuf0[q] = __ldg(gbase + (size_t)q*tstride + off0);
        gbuf1[q] = __ldg(gbase + (size_t)q*tstride + off1);
    }
    __syncthreads();

    float* hbase = hout + (size_t)b*T_*D_ + h*DH_ + e;   // written by even lane

    for (int t=0; t<T_; t+=8){
        #pragma unroll
        for (int q=0;q<8;q++){
            float gp0 = gbuf0[q], gp1 = gbuf1[q];
            if (t+q+8 < T_){
                gbuf0[q] = __ldg(gbase + (size_t)(t+q+8)*tstride + off0);
                gbuf1[q] = __ldg(gbase + (size_t)(t+q+8)*tstride + off1);
            }
            unsigned long long a0[4] = {0ull,0ull,0ull,0ull};
            unsigned long long a1[4] = {0ull,0ull,0ull,0ull};
            const ulonglong2* hp = (const ulonglong2*)h_sm[q&1];
            #pragma unroll
            for (int j=0;j<16;j++){
                ulonglong2 hv = hp[j];
                FMA2(a0[j&1],     Rp0[2*j],   hv.x);
                FMA2(a0[2+(j&1)], Rp0[2*j+1], hv.y);
                FMA2(a1[j&1],     Rp1[2*j],   hv.x);
                FMA2(a1[2+(j&1)], Rp1[2*j+1], hv.y);
            }
            float v0 = sum2(a0[0])+sum2(a0[1])+sum2(a0[2])+sum2(a0[3]) + gp0;
            float v1 = sum2(a1[0])+sum2(a1[1])+sum2(a1[2])+sum2(a1[3]) + gp1;

            // gather element e's gates from the lane pair
            const int le = lane & ~1, lo = lane | 1;
            float ip_ = __shfl_sync(0xffffffffu, v0, le);   // g=0 (i)
            float fp_ = __shfl_sync(0xffffffffu, v0, lo);   // g=1 (f)
            float zp_ = __shfl_sync(0xffffffffu, v1, le);   // g=2 (z)
            float op_ = __shfl_sync(0xffffffffu, v1, lo);   // g=3 (o)

            float hv = scan_update(ip_, fp_, zp_, op_, c, n, m);
            if (!half){
                h_sm[(q&1)^1][e] = hv;
                hbase[(size_t)(t+q)*D_] = hv;
            }
            __syncthreads();
        }
    }
}

// ------- fp16 tensor-core GEMM (fp32 staging) + LDSM fragments + fused epi ----
// mode 0: C = A*B    mode 1: Cge = gelu/up pairs (interleaved N)   mode 2: C += A*B
#define KW 20
__global__ void __launch_bounds__(256) k_gemm16(const float* __restrict__ A,
    const float* __restrict__ Bm, float* __restrict__ C, float* __restrict__ Cge,
    int N, int K, int mode)
{
    __shared__ uint32_t As[2][128*KW];
    __shared__ uint32_t Bs[2][128*KW];
    const int m0 = blockIdx.x*128, n0 = blockIdx.y*128;
    const int tid = threadIdx.x;
    const int warp=tid>>5, lane=tid&31, gid=lane>>2, tig=lane&3;
    const int wm=(warp&3)*32, wn=(warp>>2)*64;
    float acc[16][4];
    #pragma unroll
    for (int i=0;i<16;i++){ acc[i][0]=0.f; acc[i][1]=0.f; acc[i][2]=0.f; acc[i][3]=0.f; }

    const int ar  = tid>>3;
    const int ac4 = tid&7;
    const int bn  = tid&127;
    const int bkh = (tid>>7)*16;

    const int rowsel = (lane & 7) + (lane & 8);
    const int colsel = (lane & 16) ? 4 : 0;
    const uint32_t as_base = smem_u32(&As[0][0]);
    const uint32_t bs_base = smem_u32(&Bs[0][0]);

    float4 ra[4]; float rb[16];

    #pragma unroll
    for (int j=0;j<4;j++) ra[j] = *(const float4*)(A + (size_t)(m0+ar+j*32)*K + ac4*4);
    {
        const float* bp = Bm + (size_t)bkh*N + n0 + bn;
        #pragma unroll
        for (int j=0;j<16;j++) rb[j] = bp[(size_t)j*N];
    }
    #pragma unroll
    for (int j=0;j<4;j++){
        uint32_t* dst = &As[0][(ar+j*32)*KW + ac4*2];
        dst[0] = f2h2(ra[j].x, ra[j].y);
        dst[1] = f2h2(ra[j].z, ra[j].w);
    }
    #pragma unroll
    for (int w=0;w<8;w++) Bs[0][bn*KW + (bkh>>1) + w] = f2h2(rb[2*w], rb[2*w+1]);
    __syncthreads();

    const int nk = K >> 5;
    for (int i=0; i<nk; i++){
        const int cur = i&1;
        if (i+1 < nk){
            const int kb = (i+1)*32;
            #pragma unroll
            for (int j=0;j<4;j++) ra[j] = *(const float4*)(A + (size_t)(m0+ar+j*32)*K + kb + ac4*4);
            const float* bp = Bm + (size_t)(kb+bkh)*N + n0 + bn;
            #pragma unroll
            for (int j=0;j<16;j++) rb[j] = bp[(size_t)j*N];
        }
        const uint32_t abuf = as_base + (uint32_t)cur*(128*KW*4);
        const uint32_t bbuf = bs_base + (uint32_t)cur*(128*KW*4);
        #pragma unroll
        for (int ks=0;ks<2;ks++){
            const int k0w = ks*8;
            uint32_t a[2][4];
            #pragma unroll
            for (int mt=0;mt<2;mt++){
                uint32_t addr = abuf + ((wm + mt*16 + rowsel)*KW + k0w + colsel)*4;
                ldsm4(a[mt][0], a[mt][1], a[mt][2], a[mt][3], addr);
            }
            #pragma unroll
            for (int ntp=0;ntp<4;ntp++){
                uint32_t b0e,b0o,b1e,b1o;
                uint32_t addr = bbuf + ((wn + ntp*16 + rowsel)*KW + k0w + colsel)*4;
                ldsm4(b0e, b0o, b1e, b1o, addr);
                const int nt = 2*ntp;
                mma16(acc[nt],     a[0][0],a[0][1],a[0][2],a[0][3], b0e,b1e);
                mma16(acc[8+nt],   a[1][0],a[1][1],a[1][2],a[1][3], b0e,b1e);
                mma16(acc[nt+1],   a[0][0],a[0][1],a[0][2],a[0][3], b0o,b1o);
                mma16(acc[8+nt+1], a[1][0],a[1][1],a[1][2],a[1][3], b0o,b1o);
            }
        }
        if (i+1 < nk){
            const int nxt = cur^1;
            #pragma unroll
            for (int j=0;j<4;j++){
                uint32_t* dst = &As[nxt][(ar+j*32)*KW + ac4*2];
                dst[0] = f2h2(ra[j].x, ra[j].y);
                dst[1] = f2h2(ra[j].z, ra[j].w);
            }
            #pragma unroll
            for (int w=0;w<8;w++) Bs[nxt][bn*KW + (bkh>>1) + w] = f2h2(rb[2*w], rb[2*w+1]);
        }
        __syncthreads();
    }

    if (mode == 1){
        #pragma unroll
        for (int mt=0;mt<2;mt++)
          #pragma unroll
          for (int nt=0;nt<8;nt++){
            int r    = m0 + wm + mt*16 + gid;
            int cidx = n0 + wn + nt*8 + tig*2;
            int j    = cidx >> 1;
            const float* a4 = acc[mt*8+nt];
            Cge[(size_t)r*UP_ + j]     = gelu_f(a4[0]) * a4[1];
            Cge[(size_t)(r+8)*UP_ + j] = gelu_f(a4[2]) * a4[3];
          }
    } else {
        #pragma unroll
        for (int mt=0;mt<2;mt++)
          #pragma unroll
          for (int nt=0;nt<8;nt++){
            int r    = m0 + wm + mt*16 + gid;
            int cidx = n0 + wn + nt*8 + tig*2;
            float* p0 = C + (size_t)r*N + cidx;
            float* p1 = C + (size_t)(r+8)*N + cidx;
            const float* a4 = acc[mt*8+nt];
            if (mode == 2){
                p0[0]+=a4[0]; p0[1]+=a4[1];
                p1[0]+=a4[2]; p1[1]+=a4[3];
            } else {
                p0[0]=a4[0]; p0[1]=a4[1];
                p1[0]=a4[2]; p1[1]=a4[3];
            }
          }
    }
}

// ---------------- launch ------------------------------------------------------
extern "C" void kernel_launch(void* const* d_in, const int* in_sizes, int n_in,
                              void* d_out, int out_size) {
    const float* x        = (const float*)d_in[0];
    const unsigned char* mask = (const unsigned char*)d_in[1];
    const float* ln1_w    = (const float*)d_in[2];
    const float* conv_w   = (const float*)d_in[3];
    const float* conv_b   = (const float*)d_in[4];
    const float* Wg       = (const float*)d_in[5];
    const float* Rg       = (const float*)d_in[6];
    const float* bg       = (const float*)d_in[7];
    const float* gn_w     = (const float*)d_in[8];
    const float* ln2_w    = (const float*)d_in[9];
    const float* w_up     = (const float*)d_in[10];
    const float* w_down   = (const float*)d_in[11];
    const float* post_ln  = (const float*)d_in[12];
    float* out = (float*)d_out;

    float *px,*pxn,*pxc,*pg,*ph,*pge,*pwui;
    cudaGetSymbolAddress((void**)&px,  g_x);
    cudaGetSymbolAddress((void**)&pxn, g_xn);
    cudaGetSymbolAddress((void**)&pxc, g_xc);
    cudaGetSymbolAddress((void**)&pg,  g_gates);
    cudaGetSymbolAddress((void**)&ph,  g_h);
    cudaGetSymbolAddress((void**)&pge, g_ge);
    cudaGetSymbolAddress((void**)&pwui, g_wui);

    k_ilv<<<(L_*D_*2*UP_)/256, 256>>>(w_up, pwui);

    k_mask<<<NTOK_*128/256, 256>>>(x, mask, px);
    for (int l=0; l<L_; l++){
        k_ln<<<NTOK_,128>>>(px, ln1_w + l*D_, pxn);
        k_conv<<<NTOK_*128/256,256>>>(pxn, conv_w + l*4*D_, conv_b + l*D_, pxc);
        dim3 gg(NTOK_/64, NH_, 2);
        k_gates<<<gg,256>>>(pxc, pxn, Wg + (size_t)l*4*NH_*DH_*DH_, bg + l*4*NH_*DH_, pg);
        k_scan<<<64,128>>>(Rg + (size_t)l*4*NH_*DH_*DH_, pg, ph);
        k_gnres_ln<<<NTOK_,256>>>(ph, gn_w + l*D_, px, ln2_w + l*D_, pxn);
        dim3 gu(NTOK_/128, (2*UP_)/128);
        k_gemm16<<<gu,256>>>(pxn, pwui + (size_t)l*D_*2*UP_, nullptr, pge, 2*UP_, D_, 1);
        dim3 gd(NTOK_/128, D_/128);
        k_gemm16<<<gd,256>>>(pge, w_down + (size_t)l*UP_*D_, px, nullptr, D_, UP_, 2);
    }
    k_ln<<<NTOK_,128>>>(px, post_ln, out);
}